// round 15
// baseline (speedup 1.0000x reference)
#include <cuda_runtime.h>
#include <cuda_fp16.h>
#include <cstdint>

#define Tn 8192
#define Hn 1024
#define En 8
#define Fn 3584
#define F2 (2 * Fn)
#define NSLOT (Tn * 2)

#define BM 128
#define BN 128
#define BK 64                 // K halves per stage
#define LD 72                 // half stride: 144B rows (9x16B) -> conflict-free LDSM
#define ASZ (BM * LD)
#define BSZ (BN * LD)
#define STAGE (ASZ + BSZ)
#define DYN_SMEM (STAGE * 2 * 2)   // 2 stages, halves->bytes = 73728

// ---- scratch ----
__device__ __half g_xh[Tn * Hn];
__device__ __half g_w1v1[En * F2 * Hn];
__device__ __half g_w2t[En * Hn * Fn];
__device__ __half g_hmid[NSLOT * Fn];
__device__ float  g_y[NSLOT * Hn];
__device__ int    g_counts[En];
__device__ int    g_offsets[En + 1];
__device__ int    g_slot_e[NSLOT];
__device__ int    g_slot_ticket[NSLOT];
__device__ int    g_rowmap[NSLOT];
__device__ float  g_gates[NSLOT];

// ---------------------------------------------------------------------------
// cast x -> fp16; also zero the expert counters (runs before router)
__global__ void cast_x_kernel(const float* __restrict__ x) {
    if (blockIdx.x == 0 && threadIdx.x < En) g_counts[threadIdx.x] = 0;
    int i = blockIdx.x * 256 + threadIdx.x;
    if (i < Tn * Hn / 4) {
        float4 v = reinterpret_cast<const float4*>(x)[i];
        __half2* o = reinterpret_cast<__half2*>(g_xh + (size_t)i * 4);
        o[0] = __floats2half2_rn(v.x, v.y);
        o[1] = __floats2half2_rn(v.z, v.w);
    }
}
__global__ void pack_w1v1_kernel(const float* __restrict__ w1,
                                 const float* __restrict__ v1) {
    long i = (long)blockIdx.x * 256 + threadIdx.x;
    const long N = (long)En * Fn * Hn / 4;
    if (i >= N) return;
    long row = i >> 8;
    int  c   = (int)(i & 255);
    long e = row / Fn, f = row % Fn;
    float4 a = reinterpret_cast<const float4*>(w1)[i];
    float4 b = reinterpret_cast<const float4*>(v1)[i];
    __half2* ow = reinterpret_cast<__half2*>(g_w1v1 + ((e * F2 + 2 * f) * Hn) + c * 4);
    __half2* ov = reinterpret_cast<__half2*>(g_w1v1 + ((e * F2 + 2 * f + 1) * Hn) + c * 4);
    ow[0] = __floats2half2_rn(a.x, a.y); ow[1] = __floats2half2_rn(a.z, a.w);
    ov[0] = __floats2half2_rn(b.x, b.y); ov[1] = __floats2half2_rn(b.z, b.w);
}
__global__ void transpose_w2_kernel(const float* __restrict__ w2) {
    __shared__ float t[32][33];
    int e = blockIdx.z;
    int f0 = blockIdx.x * 32, h0 = blockIdx.y * 32;
    int tx = threadIdx.x, ty = threadIdx.y;
    const float* src = w2 + ((long)e * Fn + f0) * Hn + h0;
#pragma unroll
    for (int r = 0; r < 32; r += 8) t[ty + r][tx] = src[(long)(ty + r) * Hn + tx];
    __syncthreads();
    __half* dst = g_w2t + ((long)e * Hn + h0) * Fn + f0;
#pragma unroll
    for (int r = 0; r < 32; r += 8)
        dst[(long)(ty + r) * Fn + tx] = __float2half_rn(t[tx][ty + r]);
}

__global__ void router_kernel(const float* __restrict__ x,
                              const float* __restrict__ rw) {
    __shared__ float s_rw[En * Hn];
    for (int i = threadIdx.x; i < En * Hn; i += blockDim.x) s_rw[i] = rw[i];
    __syncthreads();
    int warp = threadIdx.x >> 5, lane = threadIdx.x & 31;
    int t = blockIdx.x * 8 + warp;
    if (t >= Tn) return;
    const float* xt = x + (size_t)t * Hn;
    float acc[En];
#pragma unroll
    for (int e = 0; e < En; e++) acc[e] = 0.f;
    for (int h = lane; h < Hn; h += 32) {
        float xv = xt[h];
#pragma unroll
        for (int e = 0; e < En; e++) acc[e] += xv * s_rw[e * Hn + h];
    }
#pragma unroll
    for (int e = 0; e < En; e++)
#pragma unroll
        for (int o = 16; o; o >>= 1) acc[e] += __shfl_xor_sync(0xFFFFFFFFu, acc[e], o);
    if (lane == 0) {
        int i0 = 0; float v0 = acc[0];
#pragma unroll
        for (int e = 1; e < En; e++) if (acc[e] > v0) { v0 = acc[e]; i0 = e; }
        int i1 = -1; float v1 = -3.4e38f;
#pragma unroll
        for (int e = 0; e < En; e++) if (e != i0 && acc[e] > v1) { v1 = acc[e]; i1 = e; }
        float eb = expf(v1 - v0);
        float inv = 1.f / (1.f + eb);
        g_gates[2 * t]     = inv;
        g_gates[2 * t + 1] = eb * inv;
        g_slot_e[2 * t]     = i0;
        g_slot_e[2 * t + 1] = i1;
        g_slot_ticket[2 * t]     = atomicAdd(&g_counts[i0], 1);
        g_slot_ticket[2 * t + 1] = atomicAdd(&g_counts[i1], 1);
    }
}

// single block: exclusive scan over 8 counts, then scatter all slots
__global__ void scan_scatter_kernel() {
    if (threadIdx.x == 0) {
        int s = 0;
#pragma unroll
        for (int e = 0; e < En; e++) { g_offsets[e] = s; s += g_counts[e]; }
        g_offsets[En] = s;
    }
    __syncthreads();
    for (int i = threadIdx.x; i < NSLOT; i += blockDim.x) {
        int e = g_slot_e[i];
        g_rowmap[g_offsets[e] + g_slot_ticket[i]] = i;
    }
}

// ---------------------------------------------------------------------------
__device__ __forceinline__ void mma_16816(float c[4], const unsigned a[4],
                                          unsigned b0, unsigned b1) {
    asm volatile(
        "mma.sync.aligned.m16n8k16.row.col.f32.f16.f16.f32 "
        "{%0,%1,%2,%3}, {%4,%5,%6,%7}, {%8,%9}, {%0,%1,%2,%3};\n"
        : "+f"(c[0]), "+f"(c[1]), "+f"(c[2]), "+f"(c[3])
        : "r"(a[0]), "r"(a[1]), "r"(a[2]), "r"(a[3]), "r"(b0), "r"(b1));
}
__device__ __forceinline__ void ldm_x4(unsigned& r0, unsigned& r1,
                                       unsigned& r2, unsigned& r3,
                                       const __half* p) {
    unsigned a = (unsigned)__cvta_generic_to_shared(p);
    asm volatile("ldmatrix.sync.aligned.m8n8.x4.shared.b16 {%0,%1,%2,%3}, [%4];\n"
                 : "=r"(r0), "=r"(r1), "=r"(r2), "=r"(r3) : "r"(a));
}
__device__ __forceinline__ void cp16(unsigned sdst, const void* g) {
    asm volatile("cp.async.cg.shared.global [%0], [%1], 16;\n" :: "r"(sdst), "l"(g));
}
__device__ __forceinline__ void cp16p(unsigned sdst, const void* g, bool valid) {
    int sz = valid ? 16 : 0;
    asm volatile("cp.async.cg.shared.global [%0], [%1], 16, %2;\n"
                 :: "r"(sdst), "l"(g), "r"(sz));
}

// ---------------------------------------------------------------------------
// GEMM1: hmid = silu(X W1^T) * (X V1^T), interleaved fp16 B, 128x128x64
__global__ __launch_bounds__(256)
void gemm1_kernel() {
    int e  = blockIdx.x >> 6;
    int rt = blockIdx.x & 63;
    int cnt = g_counts[e];
    int row0 = rt * BM;
    if (row0 >= cnt) return;
    int off = g_offsets[e];
    int n0  = blockIdx.y * BN;

    extern __shared__ __half sh[];      // 2 stages of [A | B]
    __shared__ int s_tok[BM];

    int tid = threadIdx.x;
    if (tid < BM) {
        int r = row0 + tid;
        s_tok[tid] = g_rowmap[off + (r < cnt ? r : 0)] >> 1;
    }
    __syncthreads();

    const __half* Bsrc = g_w1v1 + (long)e * F2 * Hn;
    // 128 rows x 8 chunks of 16B per operand; 256 thr -> each loads 4 chunks
    int cr = tid >> 1, cq0 = (tid & 1) * 4;

    auto load_stage = [&](int kt, int st) {
        int k0 = kt * BK;
        __half* A = sh + st * STAGE;
        __half* B = A + ASZ;
        const __half* ga = g_xh + (long)s_tok[cr] * Hn + k0;
#pragma unroll
        for (int q = 0; q < 4; q++) {
            unsigned d = (unsigned)__cvta_generic_to_shared(&A[cr * LD + (cq0 + q) * 8]);
            cp16(d, ga + (cq0 + q) * 8);
        }
        const __half* gb = Bsrc + (long)(n0 + cr) * Hn + k0;
#pragma unroll
        for (int q = 0; q < 4; q++) {
            unsigned d = (unsigned)__cvta_generic_to_shared(&B[cr * LD + (cq0 + q) * 8]);
            cp16(d, gb + (cq0 + q) * 8);
        }
        asm volatile("cp.async.commit_group;\n");
    };

    int warp = tid >> 5, lane = tid & 31;
    int wr = (warp & 1) * 64, wc = (warp >> 1) * 32;
    int rfr = lane >> 2, c2 = (lane & 3) * 2;
    int lrow = lane & 15, lk = (lane >> 4) << 3;
    int btI = lane >> 3;
    int brow = ((btI >> 1) << 3) + (lane & 7), bk = (btI & 1) << 3;

    float acc[4][4][4];
#pragma unroll
    for (int i = 0; i < 4; i++)
#pragma unroll
        for (int j = 0; j < 4; j++)
#pragma unroll
            for (int k = 0; k < 4; k++) acc[i][j][k] = 0.f;

    load_stage(0, 0);
    const int NK = Hn / BK;   // 16
    for (int kt = 0; kt < NK; kt++) {
        int buf = kt & 1;
        if (kt + 1 < NK) {
            load_stage(kt + 1, buf ^ 1);
            asm volatile("cp.async.wait_group 1;\n");
        } else {
            asm volatile("cp.async.wait_group 0;\n");
        }
        __syncthreads();
        const __half* A = sh + buf * STAGE;
        const __half* B = A + ASZ;
#pragma unroll
        for (int ks = 0; ks < 4; ks++) {
            int kk = ks * 16;
            unsigned b[4][2];
            ldm_x4(b[0][0], b[0][1], b[1][0], b[1][1], &B[(wc + brow) * LD + kk + bk]);
            ldm_x4(b[2][0], b[2][1], b[3][0], b[3][1], &B[(wc + 16 + brow) * LD + kk + bk]);
#pragma unroll
            for (int mt = 0; mt < 4; mt++) {
                unsigned a[4];
                ldm_x4(a[0], a[1], a[2], a[3], &A[(wr + mt * 16 + lrow) * LD + kk + lk]);
#pragma unroll
                for (int nt = 0; nt < 4; nt++)
                    mma_16816(acc[mt][nt], a, b[nt][0], b[nt][1]);
            }
        }
        __syncthreads();
    }

    // epilogue: even col = w, odd col = v of same f -> silu(w)*v
#pragma unroll
    for (int mt = 0; mt < 4; mt++) {
#pragma unroll
        for (int nt = 0; nt < 4; nt++) {
            int f = (n0 + wc + nt * 8 + c2) >> 1;
#pragma unroll
            for (int hh = 0; hh < 2; hh++) {
                int rr = row0 + wr + mt * 16 + rfr + hh * 8;
                if (rr < cnt) {
                    float w = acc[mt][nt][hh * 2 + 0];
                    float v = acc[mt][nt][hh * 2 + 1];
                    float h = w / (1.f + expf(-w)) * v;
                    g_hmid[(long)(off + rr) * Fn + f] = __float2half_rn(h);
                }
            }
        }
    }
}

// GEMM2: y[slot] = hmid @ w2t, 128x128x64
__global__ __launch_bounds__(256)
void gemm2_kernel() {
    int e  = blockIdx.x >> 6;
    int rt = blockIdx.x & 63;
    int cnt = g_counts[e];
    int row0 = rt * BM;
    if (row0 >= cnt) return;
    int off = g_offsets[e];
    int n0  = blockIdx.y * BN;

    extern __shared__ __half sh[];
    __shared__ int s_slot[BM];

    int tid = threadIdx.x;
    if (tid < BM) {
        int r = row0 + tid;
        s_slot[tid] = (r < cnt) ? g_rowmap[off + r] : -1;
    }
    __syncthreads();

    const __half* Bsrc = g_w2t + (long)e * Hn * Fn;
    const __half* Asrc = g_hmid + (long)off * Fn;
    int cr = tid >> 1, cq0 = (tid & 1) * 4;
    bool arow_ok = row0 + cr < cnt;

    auto load_stage = [&](int kt, int st) {
        int k0 = kt * BK;
        __half* A = sh + st * STAGE;
        __half* B = A + ASZ;
        const __half* ga = Asrc + (long)(row0 + cr) * Fn + k0;
#pragma unroll
        for (int q = 0; q < 4; q++) {
            unsigned d = (unsigned)__cvta_generic_to_shared(&A[cr * LD + (cq0 + q) * 8]);
            cp16p(d, ga + (cq0 + q) * 8, arow_ok);
        }
        const __half* gb = Bsrc + (long)(n0 + cr) * Fn + k0;
#pragma unroll
        for (int q = 0; q < 4; q++) {
            unsigned d = (unsigned)__cvta_generic_to_shared(&B[cr * LD + (cq0 + q) * 8]);
            cp16(d, gb + (cq0 + q) * 8);
        }
        asm volatile("cp.async.commit_group;\n");
    };

    int warp = tid >> 5, lane = tid & 31;
    int wr = (warp & 1) * 64, wc = (warp >> 1) * 32;
    int rfr = lane >> 2, c2 = (lane & 3) * 2;
    int lrow = lane & 15, lk = (lane >> 4) << 3;
    int btI = lane >> 3;
    int brow = ((btI >> 1) << 3) + (lane & 7), bk = (btI & 1) << 3;

    float acc[4][4][4];
#pragma unroll
    for (int i = 0; i < 4; i++)
#pragma unroll
        for (int j = 0; j < 4; j++)
#pragma unroll
            for (int k = 0; k < 4; k++) acc[i][j][k] = 0.f;

    load_stage(0, 0);
    const int NK = Fn / BK;   // 56
    for (int kt = 0; kt < NK; kt++) {
        int buf = kt & 1;
        if (kt + 1 < NK) {
            load_stage(kt + 1, buf ^ 1);
            asm volatile("cp.async.wait_group 1;\n");
        } else {
            asm volatile("cp.async.wait_group 0;\n");
        }
        __syncthreads();
        const __half* A = sh + buf * STAGE;
        const __half* B = A + ASZ;
#pragma unroll
        for (int ks = 0; ks < 4; ks++) {
            int kk = ks * 16;
            unsigned b[4][2];
            ldm_x4(b[0][0], b[0][1], b[1][0], b[1][1], &B[(wc + brow) * LD + kk + bk]);
            ldm_x4(b[2][0], b[2][1], b[3][0], b[3][1], &B[(wc + 16 + brow) * LD + kk + bk]);
#pragma unroll
            for (int mt = 0; mt < 4; mt++) {
                unsigned a[4];
                ldm_x4(a[0], a[1], a[2], a[3], &A[(wr + mt * 16 + lrow) * LD + kk + lk]);
#pragma unroll
                for (int nt = 0; nt < 4; nt++)
                    mma_16816(acc[mt][nt], a, b[nt][0], b[nt][1]);
            }
        }
        __syncthreads();
    }

#pragma unroll
    for (int mt = 0; mt < 4; mt++) {
#pragma unroll
        for (int hh = 0; hh < 2; hh++) {
            int slot = s_slot[wr + mt * 16 + rfr + hh * 8];
            if (slot >= 0) {
                float* yrow = g_y + (size_t)slot * Hn;
#pragma unroll
                for (int nt = 0; nt < 4; nt++) {
                    int col = n0 + wc + nt * 8 + c2;
                    float2 o;
                    o.x = acc[mt][nt][hh * 2 + 0];
                    o.y = acc[mt][nt][hh * 2 + 1];
                    *reinterpret_cast<float2*>(&yrow[col]) = o;
                }
            }
        }
    }
}

// out[t] = g0 * y[2t] + g1 * y[2t+1]
__global__ void combine_kernel(float* __restrict__ out) {
    int i = blockIdx.x * 256 + threadIdx.x;
    if (i < Tn * (Hn / 4)) {
        int t  = i / (Hn / 4);
        int c4 = i % (Hn / 4);
        float g0 = g_gates[2 * t], g1 = g_gates[2 * t + 1];
        float4 y0 = *reinterpret_cast<const float4*>(&g_y[(size_t)(2 * t) * Hn + c4 * 4]);
        float4 y1 = *reinterpret_cast<const float4*>(&g_y[(size_t)(2 * t + 1) * Hn + c4 * 4]);
        float4 o;
        o.x = g0 * y0.x + g1 * y1.x;
        o.y = g0 * y0.y + g1 * y1.y;
        o.z = g0 * y0.z + g1 * y1.z;
        o.w = g0 * y0.w + g1 * y1.w;
        *reinterpret_cast<float4*>(out + (size_t)i * 4) = o;
    }
}

// ---------------------------------------------------------------------------
extern "C" void kernel_launch(void* const* d_in, const int* in_sizes, int n_in,
                              void* d_out, int out_size) {
    const float* x  = (const float*)d_in[0];
    const float* rw = (const float*)d_in[1];
    const float* w1 = (const float*)d_in[2];
    const float* v1 = (const float*)d_in[3];
    const float* w2 = (const float*)d_in[4];
    float* out = (float*)d_out;

    static bool attr_set = false;
    if (!attr_set) {
        cudaFuncSetAttribute(gemm1_kernel,
                             cudaFuncAttributeMaxDynamicSharedMemorySize, DYN_SMEM);
        cudaFuncSetAttribute(gemm2_kernel,
                             cudaFuncAttributeMaxDynamicSharedMemorySize, DYN_SMEM);
        attr_set = true;
    }

    cast_x_kernel<<<Tn * Hn / 4 / 256, 256>>>(x);                         // 0 (+zero counts)
    router_kernel<<<Tn / 8, 256>>>(x, rw);                                 // 1
    scan_scatter_kernel<<<1, 1024>>>();                                    // 2
    pack_w1v1_kernel<<<(int)((long)En * Fn * Hn / 4 / 256), 256>>>(w1, v1);// 3
    transpose_w2_kernel<<<dim3(Fn / 32, Hn / 32, En), dim3(32, 8)>>>(w2);  // 4
    gemm1_kernel<<<dim3(En * 64, F2 / BN), 256, DYN_SMEM>>>();             // 5
    gemm2_kernel<<<dim3(En * 64, Hn / BN), 256, DYN_SMEM>>>();             // 6
    combine_kernel<<<(Tn * (Hn / 4) + 255) / 256, 256>>>(out);             // 7
}

// round 17
// speedup vs baseline: 1.1452x; 1.1452x over previous
#include <cuda_runtime.h>
#include <cuda_fp16.h>
#include <cstdint>

#define Tn 8192
#define Hn 1024
#define En 8
#define Fn 3584
#define F2 (2 * Fn)
#define NSLOT (Tn * 2)

#define BM 128
#define BN 128
#define BK 32
#define LD 40                 // half stride: 80B rows, conflict-free frag loads
#define ASZ (BM * LD)
#define BSZ (BN * LD)
#define DYN_SMEM ((ASZ + BSZ) * 2 * 2)   // two stages, halves->bytes = 40960

// ---- scratch ----
__device__ __half g_xh[Tn * Hn];
__device__ __half g_w1v1[En * F2 * Hn];
__device__ __half g_w2t[En * Hn * Fn];
__device__ __half g_hmid[NSLOT * Fn];
__device__ float  g_y[NSLOT * Hn];
__device__ int    g_counts[En];
__device__ int    g_offsets[En + 1];
__device__ int    g_slot_e[NSLOT];
__device__ int    g_slot_ticket[NSLOT];
__device__ int    g_rowmap[NSLOT];
__device__ float  g_gates[NSLOT];

// ---------------------------------------------------------------------------
// cast x -> fp16; also zero the expert counters (runs before router)
__global__ void cast_x_kernel(const float* __restrict__ x) {
    if (blockIdx.x == 0 && threadIdx.x < En) g_counts[threadIdx.x] = 0;
    int i = blockIdx.x * 256 + threadIdx.x;
    if (i < Tn * Hn / 4) {
        float4 v = reinterpret_cast<const float4*>(x)[i];
        __half2* o = reinterpret_cast<__half2*>(g_xh + (size_t)i * 4);
        o[0] = __floats2half2_rn(v.x, v.y);
        o[1] = __floats2half2_rn(v.z, v.w);
    }
}

// fused: CTAs [0,1024) route tokens; CTAs [1024, 1024+28672) pack w1/v1 -> fp16
#define ROUTER_CTAS 1024
__global__ void router_pack_kernel(const float* __restrict__ x,
                                   const float* __restrict__ rw,
                                   const float* __restrict__ w1,
                                   const float* __restrict__ v1) {
    if (blockIdx.x < ROUTER_CTAS) {
        __shared__ float s_rw[En * Hn];
        for (int i = threadIdx.x; i < En * Hn; i += blockDim.x) s_rw[i] = rw[i];
        __syncthreads();
        int warp = threadIdx.x >> 5, lane = threadIdx.x & 31;
        int t = blockIdx.x * 8 + warp;
        if (t >= Tn) return;
        const float* xt = x + (size_t)t * Hn;
        float acc[En];
#pragma unroll
        for (int e = 0; e < En; e++) acc[e] = 0.f;
        for (int h = lane; h < Hn; h += 32) {
            float xv = xt[h];
#pragma unroll
            for (int e = 0; e < En; e++) acc[e] += xv * s_rw[e * Hn + h];
        }
#pragma unroll
        for (int e = 0; e < En; e++)
#pragma unroll
            for (int o = 16; o; o >>= 1) acc[e] += __shfl_xor_sync(0xFFFFFFFFu, acc[e], o);
        if (lane == 0) {
            int i0 = 0; float v0 = acc[0];
#pragma unroll
            for (int e = 1; e < En; e++) if (acc[e] > v0) { v0 = acc[e]; i0 = e; }
            int i1 = -1; float v1 = -3.4e38f;
#pragma unroll
            for (int e = 0; e < En; e++) if (e != i0 && acc[e] > v1) { v1 = acc[e]; i1 = e; }
            float eb = expf(v1 - v0);
            float inv = 1.f / (1.f + eb);
            g_gates[2 * t]     = inv;
            g_gates[2 * t + 1] = eb * inv;
            g_slot_e[2 * t]     = i0;
            g_slot_e[2 * t + 1] = i1;
            g_slot_ticket[2 * t]     = atomicAdd(&g_counts[i0], 1);
            g_slot_ticket[2 * t + 1] = atomicAdd(&g_counts[i1], 1);
        }
    } else {
        long i = (long)(blockIdx.x - ROUTER_CTAS) * 256 + threadIdx.x;
        const long N = (long)En * Fn * Hn / 4;
        if (i >= N) return;
        long row = i >> 8;
        int  c   = (int)(i & 255);
        long e = row / Fn, f = row % Fn;
        float4 a = reinterpret_cast<const float4*>(w1)[i];
        float4 b = reinterpret_cast<const float4*>(v1)[i];
        __half2* ow = reinterpret_cast<__half2*>(g_w1v1 + ((e * F2 + 2 * f) * Hn) + c * 4);
        __half2* ov = reinterpret_cast<__half2*>(g_w1v1 + ((e * F2 + 2 * f + 1) * Hn) + c * 4);
        ow[0] = __floats2half2_rn(a.x, a.y); ow[1] = __floats2half2_rn(a.z, a.w);
        ov[0] = __floats2half2_rn(b.x, b.y); ov[1] = __floats2half2_rn(b.z, b.w);
    }
}

// single block: exclusive scan over 8 counts, then scatter all slots
__global__ void scan_scatter_kernel() {
    if (threadIdx.x == 0) {
        int s = 0;
#pragma unroll
        for (int e = 0; e < En; e++) { g_offsets[e] = s; s += g_counts[e]; }
        g_offsets[En] = s;
    }
    __syncthreads();
    for (int i = threadIdx.x; i < NSLOT; i += blockDim.x) {
        int e = g_slot_e[i];
        g_rowmap[g_offsets[e] + g_slot_ticket[i]] = i;
    }
}

// ---------------------------------------------------------------------------
__device__ __forceinline__ void mma_16816(float c[4], const unsigned a[4],
                                          unsigned b0, unsigned b1) {
    asm volatile(
        "mma.sync.aligned.m16n8k16.row.col.f32.f16.f16.f32 "
        "{%0,%1,%2,%3}, {%4,%5,%6,%7}, {%8,%9}, {%0,%1,%2,%3};\n"
        : "+f"(c[0]), "+f"(c[1]), "+f"(c[2]), "+f"(c[3])
        : "r"(a[0]), "r"(a[1]), "r"(a[2]), "r"(a[3]), "r"(b0), "r"(b1));
}
__device__ __forceinline__ void cp16(unsigned sdst, const void* g) {
    asm volatile("cp.async.cg.shared.global [%0], [%1], 16;\n" :: "r"(sdst), "l"(g));
}
__device__ __forceinline__ void cp16p(unsigned sdst, const void* g, bool valid) {
    int sz = valid ? 16 : 0;
    asm volatile("cp.async.cg.shared.global [%0], [%1], 16, %2;\n"
                 :: "r"(sdst), "l"(g), "r"(sz));
}

// ---------------------------------------------------------------------------
// GEMM1 (+embedded w2 transpose slice at blockIdx.y==56)
__global__ __launch_bounds__(256)
void gemm1_kernel(const float* __restrict__ w2) {
    int tid = threadIdx.x;

    if (blockIdx.y == F2 / BN) {   // transpose worker slice (gemm1 doesn't read w2t)
        __shared__ float t[32][33];
        int tx = tid & 31, ty8 = tid >> 5;      // 32 x 8
        for (int i = 0; i < 56; i++) {
            int tt = blockIdx.x * 56 + i;       // 512*56 = 28672 tiles
            int e = tt / ((Fn / 32) * (Hn / 32));
            int rem = tt % ((Fn / 32) * (Hn / 32));
            int f0 = (rem >> 5) * 32, h0 = (rem & 31) * 32;
            const float* src = w2 + ((long)e * Fn + f0) * Hn + h0;
#pragma unroll
            for (int r = 0; r < 32; r += 8) t[ty8 + r][tx] = src[(long)(ty8 + r) * Hn + tx];
            __syncthreads();
            __half* dst = g_w2t + ((long)e * Hn + h0) * Fn + f0;
#pragma unroll
            for (int r = 0; r < 32; r += 8)
                dst[(long)(ty8 + r) * Fn + tx] = __float2half_rn(t[tx][ty8 + r]);
            __syncthreads();
        }
        return;
    }

    int e  = blockIdx.x >> 6;
    int rt = blockIdx.x & 63;
    int cnt = g_counts[e];
    int row0 = rt * BM;
    if (row0 >= cnt) return;
    int off = g_offsets[e];
    int n0  = blockIdx.y * BN;

    extern __shared__ __half sh[];
    __half* As = sh;               // [2][ASZ]
    __half* Bs = sh + 2 * ASZ;     // [2][BSZ]
    __shared__ int s_tok[BM];

    if (tid < BM) {
        int r = row0 + tid;
        s_tok[tid] = g_rowmap[off + (r < cnt ? r : 0)] >> 1;
    }
    __syncthreads();

    const __half* Bsrc = g_w1v1 + (long)e * F2 * Hn;
    int cr = tid >> 2, cq = tid & 3;

    auto load_stage = [&](int kt, int buf) {
        int k0 = kt * BK;
#pragma unroll
        for (int it = 0; it < 2; it++) {
            int r = cr + it * 64;
            unsigned d = (unsigned)__cvta_generic_to_shared(&As[buf * ASZ + r * LD + cq * 8]);
            cp16(d, g_xh + (long)s_tok[r] * Hn + k0 + cq * 8);
        }
#pragma unroll
        for (int it = 0; it < 2; it++) {
            int r = cr + it * 64;
            unsigned d = (unsigned)__cvta_generic_to_shared(&Bs[buf * BSZ + r * LD + cq * 8]);
            cp16(d, Bsrc + (long)(n0 + r) * Hn + k0 + cq * 8);
        }
        asm volatile("cp.async.commit_group;\n");
    };

    int warp = tid >> 5, lane = tid & 31;
    int wr = (warp & 1) * 64, wc = (warp >> 1) * 32;
    int rfr = lane >> 2, c2 = (lane & 3) * 2;

    float acc[4][4][4];
#pragma unroll
    for (int i = 0; i < 4; i++)
#pragma unroll
        for (int j = 0; j < 4; j++)
#pragma unroll
            for (int k = 0; k < 4; k++) acc[i][j][k] = 0.f;

    load_stage(0, 0);
    const int NK = Hn / BK;   // 32
    for (int kt = 0; kt < NK; kt++) {
        int buf = kt & 1;
        if (kt + 1 < NK) {
            load_stage(kt + 1, buf ^ 1);
            asm volatile("cp.async.wait_group 1;\n");
        } else {
            asm volatile("cp.async.wait_group 0;\n");
        }
        __syncthreads();
        const __half* A = As + buf * ASZ;
        const __half* B = Bs + buf * BSZ;
#pragma unroll
        for (int ks = 0; ks < 2; ks++) {
            int kk = ks * 16;
            unsigned a[4][4];
#pragma unroll
            for (int mt = 0; mt < 4; mt++) {
                int mr = wr + mt * 16;
                a[mt][0] = *(const unsigned*)&A[(mr + rfr) * LD + kk + c2];
                a[mt][1] = *(const unsigned*)&A[(mr + rfr + 8) * LD + kk + c2];
                a[mt][2] = *(const unsigned*)&A[(mr + rfr) * LD + kk + c2 + 8];
                a[mt][3] = *(const unsigned*)&A[(mr + rfr + 8) * LD + kk + c2 + 8];
            }
#pragma unroll
            for (int nt = 0; nt < 4; nt++) {
                int nr = wc + nt * 8 + rfr;
                unsigned b0 = *(const unsigned*)&B[nr * LD + kk + c2];
                unsigned b1 = *(const unsigned*)&B[nr * LD + kk + c2 + 8];
#pragma unroll
                for (int mt = 0; mt < 4; mt++) mma_16816(acc[mt][nt], a[mt], b0, b1);
            }
        }
        __syncthreads();
    }

    // epilogue: even col = w, odd col = v of same f -> silu(w)*v
#pragma unroll
    for (int mt = 0; mt < 4; mt++) {
#pragma unroll
        for (int nt = 0; nt < 4; nt++) {
            int f = ((n0 + wc + nt * 8) >> 1) + (lane & 3);
#pragma unroll
            for (int hh = 0; hh < 2; hh++) {
                int rr = row0 + wr + mt * 16 + rfr + hh * 8;
                if (rr < cnt) {
                    float w = acc[mt][nt][hh * 2 + 0];
                    float v = acc[mt][nt][hh * 2 + 1];
                    float h = w / (1.f + expf(-w)) * v;
                    g_hmid[(long)(off + rr) * Fn + f] = __float2half_rn(h);
                }
            }
        }
    }
}

// GEMM2: y[slot] = hmid @ w2t  (B = g_w2t, K-major fp16)
__global__ __launch_bounds__(256)
void gemm2_kernel() {
    int e  = blockIdx.x >> 6;
    int rt = blockIdx.x & 63;
    int cnt = g_counts[e];
    int row0 = rt * BM;
    if (row0 >= cnt) return;
    int off = g_offsets[e];
    int n0  = blockIdx.y * BN;

    extern __shared__ __half sh[];
    __half* As = sh;
    __half* Bs = sh + 2 * ASZ;
    __shared__ int s_slot[BM];

    int tid = threadIdx.x;
    if (tid < BM) {
        int r = row0 + tid;
        s_slot[tid] = (r < cnt) ? g_rowmap[off + r] : -1;
    }
    __syncthreads();

    const __half* Bsrc = g_w2t + (long)e * Hn * Fn;
    const __half* Asrc = g_hmid + (long)off * Fn;
    int cr = tid >> 2, cq = tid & 3;

    auto load_stage = [&](int kt, int buf) {
        int k0 = kt * BK;
#pragma unroll
        for (int it = 0; it < 2; it++) {
            int r = cr + it * 64;
            unsigned d = (unsigned)__cvta_generic_to_shared(&As[buf * ASZ + r * LD + cq * 8]);
            cp16p(d, Asrc + (long)(row0 + r) * Fn + k0 + cq * 8, row0 + r < cnt);
        }
#pragma unroll
        for (int it = 0; it < 2; it++) {
            int r = cr + it * 64;
            unsigned d = (unsigned)__cvta_generic_to_shared(&Bs[buf * BSZ + r * LD + cq * 8]);
            cp16(d, Bsrc + (long)(n0 + r) * Fn + k0 + cq * 8);
        }
        asm volatile("cp.async.commit_group;\n");
    };

    int warp = tid >> 5, lane = tid & 31;
    int wr = (warp & 1) * 64, wc = (warp >> 1) * 32;
    int rfr = lane >> 2, c2 = (lane & 3) * 2;

    float acc[4][4][4];
#pragma unroll
    for (int i = 0; i < 4; i++)
#pragma unroll
        for (int j = 0; j < 4; j++)
#pragma unroll
            for (int k = 0; k < 4; k++) acc[i][j][k] = 0.f;

    load_stage(0, 0);
    const int NK = Fn / BK;   // 112
    for (int kt = 0; kt < NK; kt++) {
        int buf = kt & 1;
        if (kt + 1 < NK) {
            load_stage(kt + 1, buf ^ 1);
            asm volatile("cp.async.wait_group 1;\n");
        } else {
            asm volatile("cp.async.wait_group 0;\n");
        }
        __syncthreads();
        const __half* A = As + buf * ASZ;
        const __half* B = Bs + buf * BSZ;
#pragma unroll
        for (int ks = 0; ks < 2; ks++) {
            int kk = ks * 16;
            unsigned a[4][4];
#pragma unroll
            for (int mt = 0; mt < 4; mt++) {
                int mr = wr + mt * 16;
                a[mt][0] = *(const unsigned*)&A[(mr + rfr) * LD + kk + c2];
                a[mt][1] = *(const unsigned*)&A[(mr + rfr + 8) * LD + kk + c2];
                a[mt][2] = *(const unsigned*)&A[(mr + rfr) * LD + kk + c2 + 8];
                a[mt][3] = *(const unsigned*)&A[(mr + rfr + 8) * LD + kk + c2 + 8];
            }
#pragma unroll
            for (int nt = 0; nt < 4; nt++) {
                int nr = wc + nt * 8 + rfr;
                unsigned b0 = *(const unsigned*)&B[nr * LD + kk + c2];
                unsigned b1 = *(const unsigned*)&B[nr * LD + kk + c2 + 8];
#pragma unroll
                for (int mt = 0; mt < 4; mt++) mma_16816(acc[mt][nt], a[mt], b0, b1);
            }
        }
        __syncthreads();
    }

#pragma unroll
    for (int mt = 0; mt < 4; mt++) {
#pragma unroll
        for (int hh = 0; hh < 2; hh++) {
            int slot = s_slot[wr + mt * 16 + rfr + hh * 8];
            if (slot >= 0) {
                float* yrow = g_y + (size_t)slot * Hn;
#pragma unroll
                for (int nt = 0; nt < 4; nt++) {
                    int col = n0 + wc + nt * 8 + c2;
                    float2 o;
                    o.x = acc[mt][nt][hh * 2 + 0];
                    o.y = acc[mt][nt][hh * 2 + 1];
                    *reinterpret_cast<float2*>(&yrow[col]) = o;
                }
            }
        }
    }
}

// out[t] = g0 * y[2t] + g1 * y[2t+1]
__global__ void combine_kernel(float* __restrict__ out) {
    int i = blockIdx.x * 256 + threadIdx.x;
    if (i < Tn * (Hn / 4)) {
        int t  = i / (Hn / 4);
        int c4 = i % (Hn / 4);
        float g0 = g_gates[2 * t], g1 = g_gates[2 * t + 1];
        float4 y0 = *reinterpret_cast<const float4*>(&g_y[(size_t)(2 * t) * Hn + c4 * 4]);
        float4 y1 = *reinterpret_cast<const float4*>(&g_y[(size_t)(2 * t + 1) * Hn + c4 * 4]);
        float4 o;
        o.x = g0 * y0.x + g1 * y1.x;
        o.y = g0 * y0.y + g1 * y1.y;
        o.z = g0 * y0.z + g1 * y1.z;
        o.w = g0 * y0.w + g1 * y1.w;
        *reinterpret_cast<float4*>(out + (size_t)i * 4) = o;
    }
}

// ---------------------------------------------------------------------------
extern "C" void kernel_launch(void* const* d_in, const int* in_sizes, int n_in,
                              void* d_out, int out_size) {
    const float* x  = (const float*)d_in[0];
    const float* rw = (const float*)d_in[1];
    const float* w1 = (const float*)d_in[2];
    const float* v1 = (const float*)d_in[3];
    const float* w2 = (const float*)d_in[4];
    float* out = (float*)d_out;

    static bool attr_set = false;
    if (!attr_set) {
        cudaFuncSetAttribute(gemm1_kernel,
                             cudaFuncAttributeMaxDynamicSharedMemorySize, DYN_SMEM);
        cudaFuncSetAttribute(gemm2_kernel,
                             cudaFuncAttributeMaxDynamicSharedMemorySize, DYN_SMEM);
        attr_set = true;
    }

    const int PACK_CTAS = (int)((long)En * Fn * Hn / 4 / 256);   // 28672

    cast_x_kernel<<<Tn * Hn / 4 / 256, 256>>>(x);
    router_pack_kernel<<<ROUTER_CTAS + PACK_CTAS, 256>>>(x, rw, w1, v1);
    scan_scatter_kernel<<<1, 1024>>>();
    gemm1_kernel<<<dim3(En * 64, F2 / BN + 1), 256, DYN_SMEM>>>(w2);   // +transpose slice
    gemm2_kernel<<<dim3(En * 64, Hn / BN), 256, DYN_SMEM>>>();
    combine_kernel<<<(Tn * (Hn / 4) + 255) / 256, 256>>>(out);
}